// round 9
// baseline (speedup 1.0000x reference)
#include <cuda_runtime.h>
#include <cstdint>

#define B_   2
#define S_   2048
#define D_   1024
#define H_   16
#define DH_  64
#define N_   (B_ * S_)
#define K_   1024

typedef unsigned long long u64t;

__device__ float g_q[B_ * H_ * S_ * DH_];
__device__ float g_k[B_ * H_ * S_ * DH_];
__device__ float g_v[B_ * H_ * S_ * DH_];
__device__ float g_att[N_ * D_];

// Packed f32x2 helpers
__device__ __forceinline__ void fma2(u64t& c, u64t a, u64t b) {
    asm("fma.rn.f32x2 %0, %1, %2, %0;" : "+l"(c) : "l"(a), "l"(b));
}
__device__ __forceinline__ u64t mul2(u64t a, u64t b) {
    u64t r; asm("mul.rn.f32x2 %0, %1, %2;" : "=l"(r) : "l"(a), "l"(b)); return r;
}
__device__ __forceinline__ u64t pk2(float x, float y) {
    u64t r; asm("mov.b64 %0, {%1, %2};" : "=l"(r) : "f"(x), "f"(y)); return r;
}
__device__ __forceinline__ float2 up2(u64t a) {
    float2 r; asm("mov.b64 {%0, %1}, %2;" : "=f"(r.x), "=f"(r.y) : "l"(a)); return r;
}

// ---------------------------------------------------------------------------
// GEMM: C[n,o] = sum_k A[n,k]*W[o,k] + bias[o]
// Tile 128(m) x 64(o), BK=32, 256 thr, microtile 8x4, pairs along k.
// smem rows are exactly 32 floats; xor-swizzle 4*((row>>2)&7) on k.
// ---------------------------------------------------------------------------
#define SWZG(row) (4 * (((row) >> 2) & 7))

__global__ void __launch_bounds__(256, 2)
gemm2k(const float* __restrict__ A, const float* __restrict__ W,
       const float* __restrict__ bias, float* __restrict__ C, int scatter)
{
    __shared__ float As[128 * 32];
    __shared__ float Wsm[64 * 32];

    const int t  = threadIdx.x;
    const int bn = blockIdx.x;   // o block (16)
    const int bm = blockIdx.y;   // m block (32)
    const int rg = t >> 4;       // rows 8rg..+7
    const int cg = t & 15;       // cols 4cg..+3

    // global load mapping
    const int ar  = t >> 1;            // A row 0..127
    const int ak0 = (t & 1) * 16;      // A k base: 4 float4s at +0,4,8,12
    const int wr  = t >> 2;            // W row 0..63
    const int wk0 = (t & 3) * 8;       // W k base: 2 float4s at +0,4

    const float* Ag = A + (size_t)(bm * 128 + ar) * K_ + ak0;
    const float* Wg = W + (size_t)(bn * 64 + wr) * K_ + wk0;

    u64t acc[8][4];
#pragma unroll
    for (int r = 0; r < 8; r++)
#pragma unroll
        for (int c = 0; c < 4; c++) acc[r][c] = 0ULL;

    float4 pa[4], pw[2];
#pragma unroll
    for (int i = 0; i < 4; i++) pa[i] = *(const float4*)(Ag + 4 * i);
#pragma unroll
    for (int i = 0; i < 2; i++) pw[i] = *(const float4*)(Wg + 4 * i);

    const int aswz = SWZG(ar);
    const int wswz = SWZG(wr);

    for (int ch = 0; ch < 32; ch++) {
        __syncthreads();
#pragma unroll
        for (int i = 0; i < 4; i++)
            *(float4*)&As[ar * 32 + ((ak0 + 4 * i) ^ aswz)] = pa[i];
#pragma unroll
        for (int i = 0; i < 2; i++)
            *(float4*)&Wsm[wr * 32 + ((wk0 + 4 * i) ^ wswz)] = pw[i];
        __syncthreads();
        if (ch < 31) {
            const float* An = Ag + (size_t)(ch + 1) * 32;
            const float* Wn = Wg + (size_t)(ch + 1) * 32;
#pragma unroll
            for (int i = 0; i < 4; i++) pa[i] = *(const float4*)(An + 4 * i);
#pragma unroll
            for (int i = 0; i < 2; i++) pw[i] = *(const float4*)(Wn + 4 * i);
        }
#pragma unroll
        for (int k4 = 0; k4 < 32; k4 += 4) {
            ulonglong2 av[8], wv[4];
#pragma unroll
            for (int r = 0; r < 8; r++) {
                const int row = 8 * rg + r;
                av[r] = *(const ulonglong2*)&As[row * 32 + (k4 ^ SWZG(row))];
            }
#pragma unroll
            for (int c = 0; c < 4; c++) {
                const int row = 4 * cg + c;
                wv[c] = *(const ulonglong2*)&Wsm[row * 32 + (k4 ^ SWZG(row))];
            }
#pragma unroll
            for (int r = 0; r < 8; r++)
#pragma unroll
                for (int c = 0; c < 4; c++) {
                    fma2(acc[r][c], av[r].x, wv[c].x);
                    fma2(acc[r][c], av[r].y, wv[c].y);
                }
        }
    }

    // Epilogue: fold pairs, add bias, write
    const int col0 = bn * 64 + 4 * cg;
    const float4 b4 = *(const float4*)(bias + col0);
#pragma unroll
    for (int r = 0; r < 8; r++) {
        const int n = bm * 128 + 8 * rg + r;
        float2 f0 = up2(acc[r][0]);
        float2 f1 = up2(acc[r][1]);
        float2 f2 = up2(acc[r][2]);
        float2 f3 = up2(acc[r][3]);
        float4 v = make_float4(f0.x + f0.y + b4.x, f1.x + f1.y + b4.y,
                               f2.x + f2.y + b4.z, f3.x + f3.y + b4.w);
        if (scatter) {
            const int b  = n >> 11;
            const int s  = n & (S_ - 1);
            const int hh = col0 >> 6;
            const int dh = col0 & 63;
            *(float4*)(C + (((size_t)(b * H_ + hh)) * S_ + s) * DH_ + dh) = v;
        } else {
            *(float4*)(C + (size_t)n * D_ + col0) = v;
        }
    }
}

// ---------------------------------------------------------------------------
// Flash attention: 64 q-rows x 64-key blocks, 256 thr, 4x4 microtile,
// FFMA2 pairs along the reduction dim (dh for QK, key for PV).
// smem: Qs[64][68] row-major, Ks[64][68] row-major swizzled,
//       Vt[64][68] (dh-major) swizzled, Ps[64][68] scalar.
// ---------------------------------------------------------------------------
#define RP 68
#define OFF_QS  0
#define OFF_KS  (OFF_QS + 64 * RP * 4)
#define OFF_VT  (OFF_KS + 64 * RP * 4)
#define OFF_PS  (OFF_VT + 64 * RP * 4)
#define OFF_MSK (OFF_PS + 64 * RP * 4)
#define FLASH_SMEM (OFF_MSK + 256)     // 69888+256

__global__ void __launch_bounds__(256, 2)
flash_kernel(const int* __restrict__ mask, float* __restrict__ out)
{
    extern __shared__ char smc[];
    float* Qs = (float*)(smc + OFF_QS);
    float* Ks = (float*)(smc + OFF_KS);
    float* Vt = (float*)(smc + OFF_VT);
    float* Ps = (float*)(smc + OFF_PS);
    int*  msk = (int*)  (smc + OFF_MSK);

    const int qb = blockIdx.x;
    const int h  = blockIdx.y;
    const int b  = blockIdx.z;

    const float* Qg = g_q + ((size_t)(b * H_ + h)) * S_ * DH_;
    const float* Kg = g_k + ((size_t)(b * H_ + h)) * S_ * DH_;
    const float* Vg = g_v + ((size_t)(b * H_ + h)) * S_ * DH_;

    const int t  = threadIdx.x;
    const int rg = t >> 4;        // q rows 4rg..+3
    const int cg = t & 15;        // key cols / dh cols 4cg..+3

    // tile loaders: row = t>>2 (0..63), dh chunk = (t&3)*16
    const int lr  = t >> 2;
    const int ld0 = (t & 3) * 16;

    // Load Q tile (row-major, no swizzle; reads are broadcast)
#pragma unroll
    for (int i = 0; i < 4; i++) {
        float4 q4 = *(const float4*)(Qg + (size_t)(qb * 64 + lr) * DH_ + ld0 + 4 * i);
        *(float4*)&Qs[lr * RP + ld0 + 4 * i] = q4;
    }

    float m_i[4], l_i[4];
    u64t  o2[4][4];
#pragma unroll
    for (int r = 0; r < 4; r++) {
        m_i[r] = -1e30f; l_i[r] = 0.f;
#pragma unroll
        for (int d = 0; d < 4; d++) o2[r][d] = 0ULL;
    }

    for (int kb = 0; kb < S_ / 64; kb++) {
        __syncthreads();
        // K tile: row-major swizzled on dh; V tile: transposed [dh][key], swizzled on key
        {
            const int kswz = SWZG(lr);
#pragma unroll
            for (int i = 0; i < 4; i++) {
                float4 k4 = *(const float4*)(Kg + (size_t)(kb * 64 + lr) * DH_ + ld0 + 4 * i);
                *(float4*)&Ks[lr * RP + ((ld0 + 4 * i) ^ kswz)] = k4;
                float4 v4 = *(const float4*)(Vg + (size_t)(kb * 64 + lr) * DH_ + ld0 + 4 * i);
                const int d0 = ld0 + 4 * i;
                Vt[(d0 + 0) * RP + (lr ^ SWZG(d0 + 0))] = v4.x;
                Vt[(d0 + 1) * RP + (lr ^ SWZG(d0 + 1))] = v4.y;
                Vt[(d0 + 2) * RP + (lr ^ SWZG(d0 + 2))] = v4.z;
                Vt[(d0 + 3) * RP + (lr ^ SWZG(d0 + 3))] = v4.w;
            }
        }
        if (t < 64) msk[t] = mask[b * S_ + kb * 64 + t];
        __syncthreads();

        // ---- scores: pairs along dh ----
        u64t s2[4][4];
#pragma unroll
        for (int r = 0; r < 4; r++)
#pragma unroll
            for (int c = 0; c < 4; c++) s2[r][c] = 0ULL;

#pragma unroll 4
        for (int k4 = 0; k4 < 64; k4 += 4) {
            ulonglong2 qv[4], kv[4];
#pragma unroll
            for (int r = 0; r < 4; r++)
                qv[r] = *(const ulonglong2*)&Qs[(4 * rg + r) * RP + k4];
#pragma unroll
            for (int c = 0; c < 4; c++) {
                const int row = 4 * cg + c;
                kv[c] = *(const ulonglong2*)&Ks[row * RP + (k4 ^ SWZG(row))];
            }
#pragma unroll
            for (int r = 0; r < 4; r++)
#pragma unroll
                for (int c = 0; c < 4; c++) {
                    fma2(s2[r][c], qv[r].x, kv[c].x);
                    fma2(s2[r][c], qv[r].y, kv[c].y);
                }
        }

        // fold pairs, scale + mask
        float s[4][4];
#pragma unroll
        for (int r = 0; r < 4; r++)
#pragma unroll
            for (int c = 0; c < 4; c++) {
                float2 f = up2(s2[r][c]);
                s[r][c] = f.x + f.y;
            }
#pragma unroll
        for (int c = 0; c < 4; c++) {
            const bool ok = msk[4 * cg + c] != 0;
#pragma unroll
            for (int r = 0; r < 4; r++)
                s[r][c] = ok ? s[r][c] * 0.125f : -1e9f;
        }

        // online softmax (reduce across 16 cg lanes) + scalar P store
#pragma unroll
        for (int r = 0; r < 4; r++) {
            float rmax = fmaxf(fmaxf(s[r][0], s[r][1]), fmaxf(s[r][2], s[r][3]));
#pragma unroll
            for (int d = 1; d <= 8; d <<= 1)
                rmax = fmaxf(rmax, __shfl_xor_sync(0xffffffffu, rmax, d));
            const float mnew  = fmaxf(m_i[r], rmax);
            const float alpha = __expf(m_i[r] - mnew);
            float rsum = 0.f;
#pragma unroll
            for (int c = 0; c < 4; c++) {
                s[r][c] = __expf(s[r][c] - mnew);
                rsum += s[r][c];
            }
#pragma unroll
            for (int d = 1; d <= 8; d <<= 1)
                rsum += __shfl_xor_sync(0xffffffffu, rsum, d);
            l_i[r] = l_i[r] * alpha + rsum;
            m_i[r] = mnew;
            const u64t a2 = pk2(alpha, alpha);
#pragma unroll
            for (int d = 0; d < 4; d++) o2[r][d] = mul2(o2[r][d], a2);
            *(float4*)&Ps[(4 * rg + r) * RP + 4 * cg] =
                make_float4(s[r][0], s[r][1], s[r][2], s[r][3]);
        }
        __syncthreads();

        // ---- O += P @ V : pairs along key ----
#pragma unroll 4
        for (int j4 = 0; j4 < 64; j4 += 4) {
            ulonglong2 pv[4], vv[4];
#pragma unroll
            for (int r = 0; r < 4; r++)
                pv[r] = *(const ulonglong2*)&Ps[(4 * rg + r) * RP + j4];
#pragma unroll
            for (int d = 0; d < 4; d++) {
                const int row = 4 * cg + d;
                vv[d] = *(const ulonglong2*)&Vt[row * RP + (j4 ^ SWZG(row))];
            }
#pragma unroll
            for (int r = 0; r < 4; r++)
#pragma unroll
                for (int d = 0; d < 4; d++) {
                    fma2(o2[r][d], pv[r].x, vv[d].x);
                    fma2(o2[r][d], pv[r].y, vv[d].y);
                }
        }
    }

    // Epilogue: fold pairs, normalize, write
#pragma unroll
    for (int r = 0; r < 4; r++) {
        const float inv = 1.f / l_i[r];
        const int sg = qb * 64 + 4 * rg + r;
        float2 f0 = up2(o2[r][0]);
        float2 f1 = up2(o2[r][1]);
        float2 f2 = up2(o2[r][2]);
        float2 f3 = up2(o2[r][3]);
        float4 v = make_float4((f0.x + f0.y) * inv, (f1.x + f1.y) * inv,
                               (f2.x + f2.y) * inv, (f3.x + f3.y) * inv);
        *(float4*)(out + ((size_t)(b * S_ + sg)) * D_ + h * DH_ + 4 * cg) = v;
    }
}

// ---------------------------------------------------------------------------
// Launch
// ---------------------------------------------------------------------------
extern "C" void kernel_launch(void* const* d_in, const int* in_sizes, int n_in,
                              void* d_out, int out_size)
{
    (void)in_sizes; (void)n_in; (void)out_size;
    const float* x    = (const float*)d_in[0];
    const int*   mask = (const int*)  d_in[1];
    const float* Wq   = (const float*)d_in[2];
    const float* bq   = (const float*)d_in[3];
    const float* Wk   = (const float*)d_in[4];
    const float* bk   = (const float*)d_in[5];
    const float* Wv   = (const float*)d_in[6];
    const float* bv   = (const float*)d_in[7];
    const float* Wo   = (const float*)d_in[8];
    const float* bo   = (const float*)d_in[9];
    float* out = (float*)d_out;

    float *qp, *kp, *vp, *ap;
    cudaGetSymbolAddress((void**)&qp, g_q);
    cudaGetSymbolAddress((void**)&kp, g_k);
    cudaGetSymbolAddress((void**)&vp, g_v);
    cudaGetSymbolAddress((void**)&ap, g_att);

    static int attr_done = 0;
    if (!attr_done) {
        cudaFuncSetAttribute(flash_kernel,
                             cudaFuncAttributeMaxDynamicSharedMemorySize, FLASH_SMEM);
        attr_done = 1;
    }

    dim3 gg(D_ / 64, N_ / 128);   // (16, 32)
    gemm2k<<<gg, 256>>>(x, Wq, bq, qp, 1);
    gemm2k<<<gg, 256>>>(x, Wk, bk, kp, 1);
    gemm2k<<<gg, 256>>>(x, Wv, bv, vp, 1);

    flash_kernel<<<dim3(S_ / 64, H_, B_), 256, FLASH_SMEM>>>(mask, ap);

    gemm2k<<<gg, 256>>>(ap, Wo, bo, out, 0);
}

// round 11
// speedup vs baseline: 1.3610x; 1.3610x over previous
#include <cuda_runtime.h>
#include <cstdint>

// Problem constants
#define B_   2
#define S_   2048
#define D_   1024
#define H_   16
#define DH_  64
#define N_   (B_ * S_)   // 4096 tokens
#define K_   1024

// ---------------------------------------------------------------------------
// Scratch (device globals — no allocation allowed)
// ---------------------------------------------------------------------------
__device__ float g_q[B_ * H_ * S_ * DH_];   // [b][h][s][dh]
__device__ float g_k[B_ * H_ * S_ * DH_];
__device__ float g_v[B_ * H_ * S_ * DH_];
__device__ float g_att[N_ * D_];            // [n][h*64+dh]

// ---------------------------------------------------------------------------
// TN GEMM with bias, fused over up to 3 weight sets (blockIdx.z selects).
// C[n,o] = sum_k A[n,k] * W[o,k] + bias[o]
// Tiles: 64x64, BK=16, 256 threads, 4x4 microtile (R2-proven inner loop).
// scatter==1: write head-major layout [b][h][s][dh]; else row-major [n][o].
// ---------------------------------------------------------------------------
#define GP 68   // padded row stride (floats) for transposed smem tiles

__global__ void __launch_bounds__(256)
gemm_tn_bias3(const float* __restrict__ A,
              const float* __restrict__ W0, const float* __restrict__ W1,
              const float* __restrict__ W2,
              const float* __restrict__ b0, const float* __restrict__ b1,
              const float* __restrict__ b2,
              float* __restrict__ C0, float* __restrict__ C1,
              float* __restrict__ C2,
              int scatter)
{
    __shared__ float Ast[16][GP];   // [k][n-row]
    __shared__ float Wst[16][GP];   // [k][o-col]

    const int z = blockIdx.z;
    const float* W    = (z == 0) ? W0 : (z == 1) ? W1 : W2;
    const float* bias = (z == 0) ? b0 : (z == 1) ? b1 : b2;
    float*       C    = (z == 0) ? C0 : (z == 1) ? C1 : C2;

    const int bn = blockIdx.x;   // o-block
    const int bm = blockIdx.y;   // n-block
    const int t  = threadIdx.x;
    const int tx = t & 15;
    const int ty = t >> 4;

    const int lrow = t >> 2;          // 0..63
    const int lk   = (t & 3) * 4;     // 0,4,8,12

    const float* Ap = A + (size_t)(bm * 64 + lrow) * K_ + lk;
    const float* Wp = W + (size_t)(bn * 64 + lrow) * K_ + lk;

    float acc[4][4];
#pragma unroll
    for (int i = 0; i < 4; i++)
#pragma unroll
        for (int j = 0; j < 4; j++) acc[i][j] = 0.f;

    for (int k0 = 0; k0 < K_; k0 += 16) {
        float4 a4 = *(const float4*)(Ap + k0);
        float4 w4 = *(const float4*)(Wp + k0);
        __syncthreads();
        Ast[lk + 0][lrow] = a4.x; Ast[lk + 1][lrow] = a4.y;
        Ast[lk + 2][lrow] = a4.z; Ast[lk + 3][lrow] = a4.w;
        Wst[lk + 0][lrow] = w4.x; Wst[lk + 1][lrow] = w4.y;
        Wst[lk + 2][lrow] = w4.z; Wst[lk + 3][lrow] = w4.w;
        __syncthreads();
#pragma unroll
        for (int kk = 0; kk < 16; kk++) {
            float4 av = *(const float4*)&Ast[kk][ty << 2];
            float4 wv = *(const float4*)&Wst[kk][tx << 2];
            acc[0][0] += av.x * wv.x; acc[0][1] += av.x * wv.y;
            acc[0][2] += av.x * wv.z; acc[0][3] += av.x * wv.w;
            acc[1][0] += av.y * wv.x; acc[1][1] += av.y * wv.y;
            acc[1][2] += av.y * wv.z; acc[1][3] += av.y * wv.w;
            acc[2][0] += av.z * wv.x; acc[2][1] += av.z * wv.y;
            acc[2][2] += av.z * wv.z; acc[2][3] += av.z * wv.w;
            acc[3][0] += av.w * wv.x; acc[3][1] += av.w * wv.y;
            acc[3][2] += av.w * wv.z; acc[3][3] += av.w * wv.w;
        }
    }

    const int n0 = bm * 64 + (ty << 2);
    const int o0 = bn * 64 + (tx << 2);
#pragma unroll
    for (int i = 0; i < 4; i++) {
        const int n = n0 + i;
#pragma unroll
        for (int j = 0; j < 4; j++) {
            const int o = o0 + j;
            const float val = acc[i][j] + bias[o];
            if (scatter) {
                const int b  = n >> 11;           // n / S_
                const int s  = n & (S_ - 1);
                const int h  = o >> 6;
                const int dh = o & 63;
                C[(((size_t)(b * H_ + h)) * S_ + s) * DH_ + dh] = val;
            } else {
                C[(size_t)n * D_ + o] = val;
            }
        }
    }
}

// ---------------------------------------------------------------------------
// Flash attention (R2 inner loops) with P aliased onto the K tile:
// smem = Qt[64][68] + KtPs[64][68] (K tile, reused for P) + Vs[64][68] + mask
// = 51.3 KB -> 4 CTAs/SM (was 3). One extra barrier guards the K->P overwrite.
// ---------------------------------------------------------------------------
#define FP 68
#define FLASH_SMEM ((3 * 64 * FP) * 4 + 256)   // 52480 bytes

__global__ void __launch_bounds__(256)
flash_kernel(const int* __restrict__ mask, float* __restrict__ out)
{
    extern __shared__ float smf[];
    float* Qt   = smf;                 // [dh][row]  64*FP
    float* KtPs = Qt + 64 * FP;        // [dh][col] K tile; later [row][col] P tile
    float* Vs   = KtPs + 64 * FP;      // [row][dh]
    int*  msk   = (int*)(Vs + 64 * FP);

    const int qb = blockIdx.x;
    const int h  = blockIdx.y;
    const int b  = blockIdx.z;

    const float* Qg = g_q + ((size_t)(b * H_ + h)) * S_ * DH_;
    const float* Kg = g_k + ((size_t)(b * H_ + h)) * S_ * DH_;
    const float* Vg = g_v + ((size_t)(b * H_ + h)) * S_ * DH_;

    const int t  = threadIdx.x;
    const int tx = t & 15;
    const int ty = t >> 4;
    const int lrow = t >> 2;          // 0..63
    const int lq   = t & 3;           // float4 phase

    // Load Q tile transposed: Qt[dh][row]
#pragma unroll
    for (int i = 0; i < 4; i++) {
        const int dh0 = 4 * (lq + 4 * i);
        float4 q4 = *(const float4*)(Qg + (size_t)(qb * 64 + lrow) * DH_ + dh0);
        Qt[(dh0 + 0) * FP + lrow] = q4.x;
        Qt[(dh0 + 1) * FP + lrow] = q4.y;
        Qt[(dh0 + 2) * FP + lrow] = q4.z;
        Qt[(dh0 + 3) * FP + lrow] = q4.w;
    }

    float m_i[4], l_i[4], o_acc[4][4];
#pragma unroll
    for (int i = 0; i < 4; i++) {
        m_i[i] = -1e30f; l_i[i] = 0.f;
#pragma unroll
        for (int j = 0; j < 4; j++) o_acc[i][j] = 0.f;
    }

    for (int kb = 0; kb < S_ / 64; kb++) {
        __syncthreads();   // prev P@V done reading KtPs/Vs; Qt visible on iter 0
        // Load K tile transposed, V tile direct, mask slice
#pragma unroll
        for (int i = 0; i < 4; i++) {
            const int dh0 = 4 * (lq + 4 * i);
            float4 k4 = *(const float4*)(Kg + (size_t)(kb * 64 + lrow) * DH_ + dh0);
            KtPs[(dh0 + 0) * FP + lrow] = k4.x;
            KtPs[(dh0 + 1) * FP + lrow] = k4.y;
            KtPs[(dh0 + 2) * FP + lrow] = k4.z;
            KtPs[(dh0 + 3) * FP + lrow] = k4.w;
            float4 v4 = *(const float4*)(Vg + (size_t)(kb * 64 + lrow) * DH_ + dh0);
            *(float4*)&Vs[lrow * FP + dh0] = v4;
        }
        if (t < 64) msk[t] = mask[b * S_ + kb * 64 + t];
        __syncthreads();

        // Scores: s[i][j] = sum_dh Qt[dh][4ty+i] * Kt[dh][4tx+j]
        float s[4][4];
#pragma unroll
        for (int i = 0; i < 4; i++)
#pragma unroll
            for (int j = 0; j < 4; j++) s[i][j] = 0.f;
#pragma unroll 8
        for (int kk = 0; kk < 64; kk++) {
            float4 qv = *(const float4*)&Qt[kk * FP + (ty << 2)];
            float4 kv = *(const float4*)&KtPs[kk * FP + (tx << 2)];
            s[0][0] += qv.x * kv.x; s[0][1] += qv.x * kv.y;
            s[0][2] += qv.x * kv.z; s[0][3] += qv.x * kv.w;
            s[1][0] += qv.y * kv.x; s[1][1] += qv.y * kv.y;
            s[1][2] += qv.y * kv.z; s[1][3] += qv.y * kv.w;
            s[2][0] += qv.z * kv.x; s[2][1] += qv.z * kv.y;
            s[2][2] += qv.z * kv.z; s[2][3] += qv.z * kv.w;
            s[3][0] += qv.w * kv.x; s[3][1] += qv.w * kv.y;
            s[3][2] += qv.w * kv.z; s[3][3] += qv.w * kv.w;
        }

        // Scale + mask
#pragma unroll
        for (int j = 0; j < 4; j++) {
            const bool ok = msk[(tx << 2) + j] != 0;
#pragma unroll
            for (int i = 0; i < 4; i++)
                s[i][j] = ok ? s[i][j] * 0.125f : -1e9f;
        }

        // Online softmax (register-only) BEFORE the overwrite barrier
        float pv[4][4];
#pragma unroll
        for (int i = 0; i < 4; i++) {
            float rmax = fmaxf(fmaxf(s[i][0], s[i][1]), fmaxf(s[i][2], s[i][3]));
#pragma unroll
            for (int d = 1; d <= 8; d <<= 1)
                rmax = fmaxf(rmax, __shfl_xor_sync(0xffffffffu, rmax, d));
            const float mnew  = fmaxf(m_i[i], rmax);
            const float alpha = __expf(m_i[i] - mnew);
            float rsum = 0.f;
#pragma unroll
            for (int j = 0; j < 4; j++) {
                pv[i][j] = __expf(s[i][j] - mnew);
                rsum += pv[i][j];
            }
#pragma unroll
            for (int d = 1; d <= 8; d <<= 1)
                rsum += __shfl_xor_sync(0xffffffffu, rsum, d);
            l_i[i] = l_i[i] * alpha + rsum;
            m_i[i] = mnew;
#pragma unroll
            for (int j = 0; j < 4; j++) o_acc[i][j] *= alpha;
        }

        __syncthreads();   // all lanes done reading K tile -> safe to overwrite with P
#pragma unroll
        for (int i = 0; i < 4; i++)
            *(float4*)&KtPs[((ty << 2) + i) * FP + (tx << 2)] =
                make_float4(pv[i][0], pv[i][1], pv[i][2], pv[i][3]);
        __syncthreads();   // P visible

        // O += P @ V
#pragma unroll 8
        for (int jj = 0; jj < 64; jj++) {
            const float4 vv = *(const float4*)&Vs[jj * FP + (tx << 2)];
            const float p0 = KtPs[((ty << 2) + 0) * FP + jj];
            const float p1 = KtPs[((ty << 2) + 1) * FP + jj];
            const float p2 = KtPs[((ty << 2) + 2) * FP + jj];
            const float p3 = KtPs[((ty << 2) + 3) * FP + jj];
            o_acc[0][0] += p0 * vv.x; o_acc[0][1] += p0 * vv.y;
            o_acc[0][2] += p0 * vv.z; o_acc[0][3] += p0 * vv.w;
            o_acc[1][0] += p1 * vv.x; o_acc[1][1] += p1 * vv.y;
            o_acc[1][2] += p1 * vv.z; o_acc[1][3] += p1 * vv.w;
            o_acc[2][0] += p2 * vv.x; o_acc[2][1] += p2 * vv.y;
            o_acc[2][2] += p2 * vv.z; o_acc[2][3] += p2 * vv.w;
            o_acc[3][0] += p3 * vv.x; o_acc[3][1] += p3 * vv.y;
            o_acc[3][2] += p3 * vv.z; o_acc[3][3] += p3 * vv.w;
        }
    }

    // Epilogue: normalize and write to [n][h*64+dh] layout
#pragma unroll
    for (int i = 0; i < 4; i++) {
        const float inv = 1.f / l_i[i];
        const int sg = qb * 64 + (ty << 2) + i;
#pragma unroll
        for (int j = 0; j < 4; j++) {
            out[((size_t)(b * S_ + sg)) * D_ + h * DH_ + (tx << 2) + j] =
                o_acc[i][j] * inv;
        }
    }
}

// ---------------------------------------------------------------------------
// Launch
// ---------------------------------------------------------------------------
extern "C" void kernel_launch(void* const* d_in, const int* in_sizes, int n_in,
                              void* d_out, int out_size)
{
    (void)in_sizes; (void)n_in; (void)out_size;
    const float* x    = (const float*)d_in[0];
    const int*   mask = (const int*)  d_in[1];
    const float* Wq   = (const float*)d_in[2];
    const float* bq   = (const float*)d_in[3];
    const float* Wk   = (const float*)d_in[4];
    const float* bk   = (const float*)d_in[5];
    const float* Wv   = (const float*)d_in[6];
    const float* bv   = (const float*)d_in[7];
    const float* Wo   = (const float*)d_in[8];
    const float* bo   = (const float*)d_in[9];
    float* out = (float*)d_out;

    float *qp, *kp, *vp, *ap;
    cudaGetSymbolAddress((void**)&qp, g_q);
    cudaGetSymbolAddress((void**)&kp, g_k);
    cudaGetSymbolAddress((void**)&vp, g_v);
    cudaGetSymbolAddress((void**)&ap, g_att);

    static int attr_done = 0;
    if (!attr_done) {
        cudaFuncSetAttribute(flash_kernel,
                             cudaFuncAttributeMaxDynamicSharedMemorySize, FLASH_SMEM);
        attr_done = 1;
    }

    // Fused Q/K/V projections: one launch, z selects weight set
    gemm_tn_bias3<<<dim3(D_ / 64, N_ / 64, 3), 256>>>(
        x, Wq, Wk, Wv, bq, bk, bv, qp, kp, vp, 1);

    flash_kernel<<<dim3(S_ / 64, H_, B_), 256, FLASH_SMEM>>>(mask, ap);

    // Output projection
    gemm_tn_bias3<<<dim3(D_ / 64, N_ / 64, 1), 256>>>(
        ap, Wo, Wo, Wo, bo, bo, bo, out, out, out, 0);
}

// round 12
// speedup vs baseline: 1.4388x; 1.0572x over previous
#include <cuda_runtime.h>
#include <cstdint>

// Problem constants
#define B_   2
#define S_   2048
#define D_   1024
#define H_   16
#define DH_  64
#define N_   (B_ * S_)   // 4096 tokens
#define K_   1024

// ---------------------------------------------------------------------------
// Scratch (device globals — no allocation allowed)
// ---------------------------------------------------------------------------
__device__ float g_q[B_ * H_ * S_ * DH_];   // [b][h][s][dh]
__device__ float g_k[B_ * H_ * S_ * DH_];
__device__ float g_v[B_ * H_ * S_ * DH_];
__device__ float g_att[N_ * D_];            // [n][h*64+dh]

// ---------------------------------------------------------------------------
// TN GEMM, 8x4 microtile: C[n,o] = sum_k A[n,k]*W[o,k] + bias[o]
// Tile 64x64, BK=16, 128 threads (8 ty x 16 tx), z selects weight set.
// Per k-step per thread: 3 LDS.128 : 32 FFMA -> FFMA-bound (was 1:1 at 4x4).
// scatter==1: write head-major [b][h][s][dh]; else row-major [n][o].
// ---------------------------------------------------------------------------
#define GP 68   // padded row stride (floats) for transposed smem tiles

__global__ void __launch_bounds__(128)
gemm84(const float* __restrict__ A,
       const float* __restrict__ W0, const float* __restrict__ W1,
       const float* __restrict__ W2,
       const float* __restrict__ b0, const float* __restrict__ b1,
       const float* __restrict__ b2,
       float* __restrict__ C0, float* __restrict__ C1, float* __restrict__ C2,
       int scatter)
{
    __shared__ float Ast[16][GP];   // [k][m-row]
    __shared__ float Wst[16][GP];   // [k][o-col]

    const int z = blockIdx.z;
    const float* W    = (z == 0) ? W0 : (z == 1) ? W1 : W2;
    const float* bias = (z == 0) ? b0 : (z == 1) ? b1 : b2;
    float*       C    = (z == 0) ? C0 : (z == 1) ? C1 : C2;

    const int bn = blockIdx.x;   // o-block (16)
    const int bm = blockIdx.y;   // n-block (64)
    const int t  = threadIdx.x;
    const int tx = t & 15;       // cols 4tx..+3
    const int ty = t >> 4;       // rows 8ty..+7

    const int lrow = t >> 1;         // 0..63
    const int lk   = (t & 1) * 8;    // 0 or 8

    const float* Ap = A + (size_t)(bm * 64 + lrow) * K_ + lk;
    const float* Wp = W + (size_t)(bn * 64 + lrow) * K_ + lk;

    float acc[8][4];
#pragma unroll
    for (int r = 0; r < 8; r++)
#pragma unroll
        for (int j = 0; j < 4; j++) acc[r][j] = 0.f;

    float4 a0 = *(const float4*)(Ap);
    float4 a1 = *(const float4*)(Ap + 4);
    float4 w0 = *(const float4*)(Wp);
    float4 w1 = *(const float4*)(Wp + 4);

    for (int c = 0; c < 64; c++) {
        __syncthreads();
        Ast[lk + 0][lrow] = a0.x; Ast[lk + 1][lrow] = a0.y;
        Ast[lk + 2][lrow] = a0.z; Ast[lk + 3][lrow] = a0.w;
        Ast[lk + 4][lrow] = a1.x; Ast[lk + 5][lrow] = a1.y;
        Ast[lk + 6][lrow] = a1.z; Ast[lk + 7][lrow] = a1.w;
        Wst[lk + 0][lrow] = w0.x; Wst[lk + 1][lrow] = w0.y;
        Wst[lk + 2][lrow] = w0.z; Wst[lk + 3][lrow] = w0.w;
        Wst[lk + 4][lrow] = w1.x; Wst[lk + 5][lrow] = w1.y;
        Wst[lk + 6][lrow] = w1.z; Wst[lk + 7][lrow] = w1.w;
        __syncthreads();
        if (c < 63) {
            const float* An = Ap + (size_t)(c + 1) * 16;
            const float* Wn = Wp + (size_t)(c + 1) * 16;
            a0 = *(const float4*)(An);
            a1 = *(const float4*)(An + 4);
            w0 = *(const float4*)(Wn);
            w1 = *(const float4*)(Wn + 4);
        }
#pragma unroll
        for (int kk = 0; kk < 16; kk++) {
            const float4 av0 = *(const float4*)&Ast[kk][(ty << 3)];
            const float4 av1 = *(const float4*)&Ast[kk][(ty << 3) + 4];
            const float4 wv  = *(const float4*)&Wst[kk][(tx << 2)];
            acc[0][0] += av0.x * wv.x; acc[0][1] += av0.x * wv.y;
            acc[0][2] += av0.x * wv.z; acc[0][3] += av0.x * wv.w;
            acc[1][0] += av0.y * wv.x; acc[1][1] += av0.y * wv.y;
            acc[1][2] += av0.y * wv.z; acc[1][3] += av0.y * wv.w;
            acc[2][0] += av0.z * wv.x; acc[2][1] += av0.z * wv.y;
            acc[2][2] += av0.z * wv.z; acc[2][3] += av0.z * wv.w;
            acc[3][0] += av0.w * wv.x; acc[3][1] += av0.w * wv.y;
            acc[3][2] += av0.w * wv.z; acc[3][3] += av0.w * wv.w;
            acc[4][0] += av1.x * wv.x; acc[4][1] += av1.x * wv.y;
            acc[4][2] += av1.x * wv.z; acc[4][3] += av1.x * wv.w;
            acc[5][0] += av1.y * wv.x; acc[5][1] += av1.y * wv.y;
            acc[5][2] += av1.y * wv.z; acc[5][3] += av1.y * wv.w;
            acc[6][0] += av1.z * wv.x; acc[6][1] += av1.z * wv.y;
            acc[6][2] += av1.z * wv.z; acc[6][3] += av1.z * wv.w;
            acc[7][0] += av1.w * wv.x; acc[7][1] += av1.w * wv.y;
            acc[7][2] += av1.w * wv.z; acc[7][3] += av1.w * wv.w;
        }
    }

    // Epilogue: 4 contiguous cols per row -> float4 stores
    const int o0 = bn * 64 + (tx << 2);
    const float4 b4 = *(const float4*)(bias + o0);
#pragma unroll
    for (int r = 0; r < 8; r++) {
        const int n = bm * 64 + (ty << 3) + r;
        float4 v = make_float4(acc[r][0] + b4.x, acc[r][1] + b4.y,
                               acc[r][2] + b4.z, acc[r][3] + b4.w);
        if (scatter) {
            const int b  = n >> 11;           // n / S_
            const int s  = n & (S_ - 1);
            const int hh = o0 >> 6;
            const int dh = o0 & 63;
            *(float4*)(C + (((size_t)(b * H_ + hh)) * S_ + s) * DH_ + dh) = v;
        } else {
            *(float4*)(C + (size_t)n * D_ + o0) = v;
        }
    }
}

// ---------------------------------------------------------------------------
// Flash attention (R11-proven): P aliased onto K tile, 4 CTAs/SM.
// ---------------------------------------------------------------------------
#define FP 68
#define FLASH_SMEM ((3 * 64 * FP) * 4 + 256)   // 52480 bytes

__global__ void __launch_bounds__(256)
flash_kernel(const int* __restrict__ mask, float* __restrict__ out)
{
    extern __shared__ float smf[];
    float* Qt   = smf;                 // [dh][row]  64*FP
    float* KtPs = Qt + 64 * FP;        // [dh][col] K tile; later [row][col] P tile
    float* Vs   = KtPs + 64 * FP;      // [row][dh]
    int*  msk   = (int*)(Vs + 64 * FP);

    const int qb = blockIdx.x;
    const int h  = blockIdx.y;
    const int b  = blockIdx.z;

    const float* Qg = g_q + ((size_t)(b * H_ + h)) * S_ * DH_;
    const float* Kg = g_k + ((size_t)(b * H_ + h)) * S_ * DH_;
    const float* Vg = g_v + ((size_t)(b * H_ + h)) * S_ * DH_;

    const int t  = threadIdx.x;
    const int tx = t & 15;
    const int ty = t >> 4;
    const int lrow = t >> 2;          // 0..63
    const int lq   = t & 3;           // float4 phase

    // Load Q tile transposed: Qt[dh][row]
#pragma unroll
    for (int i = 0; i < 4; i++) {
        const int dh0 = 4 * (lq + 4 * i);
        float4 q4 = *(const float4*)(Qg + (size_t)(qb * 64 + lrow) * DH_ + dh0);
        Qt[(dh0 + 0) * FP + lrow] = q4.x;
        Qt[(dh0 + 1) * FP + lrow] = q4.y;
        Qt[(dh0 + 2) * FP + lrow] = q4.z;
        Qt[(dh0 + 3) * FP + lrow] = q4.w;
    }

    float m_i[4], l_i[4], o_acc[4][4];
#pragma unroll
    for (int i = 0; i < 4; i++) {
        m_i[i] = -1e30f; l_i[i] = 0.f;
#pragma unroll
        for (int j = 0; j < 4; j++) o_acc[i][j] = 0.f;
    }

    for (int kb = 0; kb < S_ / 64; kb++) {
        __syncthreads();   // prev P@V done reading KtPs/Vs; Qt visible on iter 0
#pragma unroll
        for (int i = 0; i < 4; i++) {
            const int dh0 = 4 * (lq + 4 * i);
            float4 k4 = *(const float4*)(Kg + (size_t)(kb * 64 + lrow) * DH_ + dh0);
            KtPs[(dh0 + 0) * FP + lrow] = k4.x;
            KtPs[(dh0 + 1) * FP + lrow] = k4.y;
            KtPs[(dh0 + 2) * FP + lrow] = k4.z;
            KtPs[(dh0 + 3) * FP + lrow] = k4.w;
            float4 v4 = *(const float4*)(Vg + (size_t)(kb * 64 + lrow) * DH_ + dh0);
            *(float4*)&Vs[lrow * FP + dh0] = v4;
        }
        if (t < 64) msk[t] = mask[b * S_ + kb * 64 + t];
        __syncthreads();

        // Scores
        float s[4][4];
#pragma unroll
        for (int i = 0; i < 4; i++)
#pragma unroll
            for (int j = 0; j < 4; j++) s[i][j] = 0.f;
#pragma unroll 8
        for (int kk = 0; kk < 64; kk++) {
            float4 qv = *(const float4*)&Qt[kk * FP + (ty << 2)];
            float4 kv = *(const float4*)&KtPs[kk * FP + (tx << 2)];
            s[0][0] += qv.x * kv.x; s[0][1] += qv.x * kv.y;
            s[0][2] += qv.x * kv.z; s[0][3] += qv.x * kv.w;
            s[1][0] += qv.y * kv.x; s[1][1] += qv.y * kv.y;
            s[1][2] += qv.y * kv.z; s[1][3] += qv.y * kv.w;
            s[2][0] += qv.z * kv.x; s[2][1] += qv.z * kv.y;
            s[2][2] += qv.z * kv.z; s[2][3] += qv.z * kv.w;
            s[3][0] += qv.w * kv.x; s[3][1] += qv.w * kv.y;
            s[3][2] += qv.w * kv.z; s[3][3] += qv.w * kv.w;
        }

        // Scale + mask
#pragma unroll
        for (int j = 0; j < 4; j++) {
            const bool ok = msk[(tx << 2) + j] != 0;
#pragma unroll
            for (int i = 0; i < 4; i++)
                s[i][j] = ok ? s[i][j] * 0.125f : -1e9f;
        }

        // Online softmax (register-only) before the overwrite barrier
        float pv[4][4];
#pragma unroll
        for (int i = 0; i < 4; i++) {
            float rmax = fmaxf(fmaxf(s[i][0], s[i][1]), fmaxf(s[i][2], s[i][3]));
#pragma unroll
            for (int d = 1; d <= 8; d <<= 1)
                rmax = fmaxf(rmax, __shfl_xor_sync(0xffffffffu, rmax, d));
            const float mnew  = fmaxf(m_i[i], rmax);
            const float alpha = __expf(m_i[i] - mnew);
            float rsum = 0.f;
#pragma unroll
            for (int j = 0; j < 4; j++) {
                pv[i][j] = __expf(s[i][j] - mnew);
                rsum += pv[i][j];
            }
#pragma unroll
            for (int d = 1; d <= 8; d <<= 1)
                rsum += __shfl_xor_sync(0xffffffffu, rsum, d);
            l_i[i] = l_i[i] * alpha + rsum;
            m_i[i] = mnew;
#pragma unroll
            for (int j = 0; j < 4; j++) o_acc[i][j] *= alpha;
        }

        __syncthreads();   // K tile fully consumed -> safe to overwrite with P
#pragma unroll
        for (int i = 0; i < 4; i++)
            *(float4*)&KtPs[((ty << 2) + i) * FP + (tx << 2)] =
                make_float4(pv[i][0], pv[i][1], pv[i][2], pv[i][3]);
        __syncthreads();   // P visible

        // O += P @ V
#pragma unroll 8
        for (int jj = 0; jj < 64; jj++) {
            const float4 vv = *(const float4*)&Vs[jj * FP + (tx << 2)];
            const float p0 = KtPs[((ty << 2) + 0) * FP + jj];
            const float p1 = KtPs[((ty << 2) + 1) * FP + jj];
            const float p2 = KtPs[((ty << 2) + 2) * FP + jj];
            const float p3 = KtPs[((ty << 2) + 3) * FP + jj];
            o_acc[0][0] += p0 * vv.x; o_acc[0][1] += p0 * vv.y;
            o_acc[0][2] += p0 * vv.z; o_acc[0][3] += p0 * vv.w;
            o_acc[1][0] += p1 * vv.x; o_acc[1][1] += p1 * vv.y;
            o_acc[1][2] += p1 * vv.z; o_acc[1][3] += p1 * vv.w;
            o_acc[2][0] += p2 * vv.x; o_acc[2][1] += p2 * vv.y;
            o_acc[2][2] += p2 * vv.z; o_acc[2][3] += p2 * vv.w;
            o_acc[3][0] += p3 * vv.x; o_acc[3][1] += p3 * vv.y;
            o_acc[3][2] += p3 * vv.z; o_acc[3][3] += p3 * vv.w;
        }
    }

    // Epilogue
#pragma unroll
    for (int i = 0; i < 4; i++) {
        const float inv = 1.f / l_i[i];
        const int sg = qb * 64 + (ty << 2) + i;
#pragma unroll
        for (int j = 0; j < 4; j++) {
            out[((size_t)(b * S_ + sg)) * D_ + h * DH_ + (tx << 2) + j] =
                o_acc[i][j] * inv;
        }
    }
}

// ---------------------------------------------------------------------------
// Launch
// ---------------------------------------------------------------------------
extern "C" void kernel_launch(void* const* d_in, const int* in_sizes, int n_in,
                              void* d_out, int out_size)
{
    (void)in_sizes; (void)n_in; (void)out_size;
    const float* x    = (const float*)d_in[0];
    const int*   mask = (const int*)  d_in[1];
    const float* Wq   = (const float*)d_in[2];
    const float* bq   = (const float*)d_in[3];
    const float* Wk   = (const float*)d_in[4];
    const float* bk   = (const float*)d_in[5];
    const float* Wv   = (const float*)d_in[6];
    const float* bv   = (const float*)d_in[7];
    const float* Wo   = (const float*)d_in[8];
    const float* bo   = (const float*)d_in[9];
    float* out = (float*)d_out;

    float *qp, *kp, *vp, *ap;
    cudaGetSymbolAddress((void**)&qp, g_q);
    cudaGetSymbolAddress((void**)&kp, g_k);
    cudaGetSymbolAddress((void**)&vp, g_v);
    cudaGetSymbolAddress((void**)&ap, g_att);

    static int attr_done = 0;
    if (!attr_done) {
        cudaFuncSetAttribute(flash_kernel,
                             cudaFuncAttributeMaxDynamicSharedMemorySize, FLASH_SMEM);
        attr_done = 1;
    }

    // Fused Q/K/V projections: one launch, z selects weight set
    gemm84<<<dim3(D_ / 64, N_ / 64, 3), 128>>>(
        x, Wq, Wk, Wv, bq, bk, bv, qp, kp, vp, 1);

    flash_kernel<<<dim3(S_ / 64, H_, B_), 256, FLASH_SMEM>>>(mask, ap);

    // Output projection
    gemm84<<<dim3(D_ / 64, N_ / 64, 1), 128>>>(
        ap, Wo, Wo, Wo, bo, bo, bo, out, out, out, 0);
}

// round 13
// speedup vs baseline: 2.0506x; 1.4252x over previous
#include <cuda_runtime.h>
#include <cuda_fp16.h>
#include <cstdint>

// Problem constants
#define B_   2
#define S_   2048
#define D_   1024
#define H_   16
#define DH_  64
#define N_   (B_ * S_)   // 4096 tokens
#define K_   1024

// ---------------------------------------------------------------------------
// Scratch (device globals — no allocation allowed)
// ---------------------------------------------------------------------------
__device__ float g_q[B_ * H_ * S_ * DH_];   // [b][h][s][dh]
__device__ float g_k[B_ * H_ * S_ * DH_];
__device__ float g_v[B_ * H_ * S_ * DH_];
__device__ float g_att[N_ * D_];            // [n][h*64+dh]

// ---------------------------------------------------------------------------
// fp16 HMMA helpers
// ---------------------------------------------------------------------------
__device__ __forceinline__ uint32_t f2h2(float x, float y) {
    __half2 h = __floats2half2_rn(x, y);
    return *(uint32_t*)&h;
}
__device__ __forceinline__ void mma_f16(float* c, const uint32_t* a, const uint32_t* b) {
    asm volatile(
        "mma.sync.aligned.m16n8k16.row.col.f32.f16.f16.f32 "
        "{%0,%1,%2,%3}, {%4,%5,%6,%7}, {%8,%9}, {%0,%1,%2,%3};"
        : "+f"(c[0]), "+f"(c[1]), "+f"(c[2]), "+f"(c[3])
        : "r"(a[0]), "r"(a[1]), "r"(a[2]), "r"(a[3]), "r"(b[0]), "r"(b[1]));
}

// ---------------------------------------------------------------------------
// fp16 mma.sync TN GEMM: C[n,o] = sum_k A[n,k]*W[o,k] + bias[o]
// Tile 128x128, K-chunk 32 (2 k16 steps), 256 thr = 8 warps (2m x 4n),
// warp tile 64x32 = 4x4 m16n8k16 frags. z selects weight set.
// ---------------------------------------------------------------------------
#define KPH 40   // smem k-stride in halves (bank-conflict-free frag loads)

__global__ void __launch_bounds__(256)
gemmh(const float* __restrict__ A,
      const float* __restrict__ W0, const float* __restrict__ W1,
      const float* __restrict__ W2,
      const float* __restrict__ b0, const float* __restrict__ b1,
      const float* __restrict__ b2,
      float* __restrict__ C0, float* __restrict__ C1, float* __restrict__ C2,
      int scatter)
{
    __shared__ uint16_t Ah[128 * KPH];
    __shared__ uint16_t Bh[128 * KPH];

    const int z = blockIdx.z;
    const float* W    = (z == 0) ? W0 : (z == 1) ? W1 : W2;
    const float* bias = (z == 0) ? b0 : (z == 1) ? b1 : b2;
    float*       C    = (z == 0) ? C0 : (z == 1) ? C1 : C2;

    const int t    = threadIdx.x;
    const int wid  = t >> 5;
    const int lane = t & 31;
    const int bn = blockIdx.x;   // o block (8)
    const int bm = blockIdx.y;   // token block (32)

    const int wr = (wid & 1) << 6;   // warp m offset: 0 / 64
    const int wc = (wid >> 1) << 5;  // warp n offset: 0..96
    const int g   = lane >> 2;       // 0..7
    const int tig = lane & 3;        // 0..3

    // gmem load mapping: row = t>>1 (0..127), k chunk half = (t&1)*16
    const int lrow = t >> 1;
    const int lkc  = (t & 1) * 16;

    const float* Ag = A + (size_t)(bm * 128 + lrow) * K_ + lkc;
    const float* Wg = W + (size_t)(bn * 128 + lrow) * K_ + lkc;

    float acc[4][4][4];
#pragma unroll
    for (int mt = 0; mt < 4; mt++)
#pragma unroll
        for (int nt = 0; nt < 4; nt++)
#pragma unroll
            for (int r = 0; r < 4; r++) acc[mt][nt][r] = 0.f;

    float4 pa[4], pb[4];
#pragma unroll
    for (int i = 0; i < 4; i++) {
        pa[i] = *(const float4*)(Ag + 4 * i);
        pb[i] = *(const float4*)(Wg + 4 * i);
    }

    for (int c = 0; c < 32; c++) {
        __syncthreads();
#pragma unroll
        for (int i = 0; i < 4; i++) {
            *(uint2*)&Ah[lrow * KPH + lkc + 4 * i] =
                make_uint2(f2h2(pa[i].x, pa[i].y), f2h2(pa[i].z, pa[i].w));
            *(uint2*)&Bh[lrow * KPH + lkc + 4 * i] =
                make_uint2(f2h2(pb[i].x, pb[i].y), f2h2(pb[i].z, pb[i].w));
        }
        __syncthreads();
        if (c < 31) {
            const float* An = Ag + (size_t)(c + 1) * 32;
            const float* Wn = Wg + (size_t)(c + 1) * 32;
#pragma unroll
            for (int i = 0; i < 4; i++) {
                pa[i] = *(const float4*)(An + 4 * i);
                pb[i] = *(const float4*)(Wn + 4 * i);
            }
        }
#pragma unroll
        for (int ks = 0; ks < 2; ks++) {
            const int k0 = 16 * ks + 2 * tig;
            uint32_t af[4][4], bf[4][2];
#pragma unroll
            for (int mt = 0; mt < 4; mt++) {
                const int r = wr + 16 * mt + g;
                af[mt][0] = *(const uint32_t*)&Ah[r * KPH + k0];
                af[mt][1] = *(const uint32_t*)&Ah[(r + 8) * KPH + k0];
                af[mt][2] = *(const uint32_t*)&Ah[r * KPH + k0 + 8];
                af[mt][3] = *(const uint32_t*)&Ah[(r + 8) * KPH + k0 + 8];
            }
#pragma unroll
            for (int nt = 0; nt < 4; nt++) {
                const int o = wc + 8 * nt + g;
                bf[nt][0] = *(const uint32_t*)&Bh[o * KPH + k0];
                bf[nt][1] = *(const uint32_t*)&Bh[o * KPH + k0 + 8];
            }
#pragma unroll
            for (int mt = 0; mt < 4; mt++)
#pragma unroll
                for (int nt = 0; nt < 4; nt++)
                    mma_f16(acc[mt][nt], af[mt], bf[nt]);
        }
    }

    // Epilogue (verified fragment layout from R4): c0,c1 at (row, col/col+1),
    // c2,c3 at row+8.
    const int rbase = bm * 128 + wr + g;
    const int cbase = bn * 128 + wc + 2 * tig;
#pragma unroll
    for (int mt = 0; mt < 4; mt++) {
#pragma unroll
        for (int nt = 0; nt < 4; nt++) {
            const int col = cbase + nt * 8;
            const float bx = bias[col], by = bias[col + 1];
#pragma unroll
            for (int h2 = 0; h2 < 2; h2++) {
                const int n = rbase + mt * 16 + 8 * h2;
                float2 v;
                v.x = acc[mt][nt][2 * h2 + 0] + bx;
                v.y = acc[mt][nt][2 * h2 + 1] + by;
                if (scatter) {
                    const int b  = n >> 11;
                    const int s  = n & (S_ - 1);
                    const int hh = col >> 6;
                    const int dh = col & 63;
                    *(float2*)(C + (((size_t)(b * H_ + hh)) * S_ + s) * DH_ + dh) = v;
                } else {
                    *(float2*)(C + (size_t)n * D_ + col) = v;
                }
            }
        }
    }
}

// ---------------------------------------------------------------------------
// Flash attention (R12-proven): P aliased onto K tile, 4 CTAs/SM, fp32.
// ---------------------------------------------------------------------------
#define FP 68
#define FLASH_SMEM ((3 * 64 * FP) * 4 + 256)   // 52480 bytes

__global__ void __launch_bounds__(256)
flash_kernel(const int* __restrict__ mask, float* __restrict__ out)
{
    extern __shared__ float smf[];
    float* Qt   = smf;
    float* KtPs = Qt + 64 * FP;
    float* Vs   = KtPs + 64 * FP;
    int*  msk   = (int*)(Vs + 64 * FP);

    const int qb = blockIdx.x;
    const int h  = blockIdx.y;
    const int b  = blockIdx.z;

    const float* Qg = g_q + ((size_t)(b * H_ + h)) * S_ * DH_;
    const float* Kg = g_k + ((size_t)(b * H_ + h)) * S_ * DH_;
    const float* Vg = g_v + ((size_t)(b * H_ + h)) * S_ * DH_;

    const int t  = threadIdx.x;
    const int tx = t & 15;
    const int ty = t >> 4;
    const int lrow = t >> 2;
    const int lq   = t & 3;

#pragma unroll
    for (int i = 0; i < 4; i++) {
        const int dh0 = 4 * (lq + 4 * i);
        float4 q4 = *(const float4*)(Qg + (size_t)(qb * 64 + lrow) * DH_ + dh0);
        Qt[(dh0 + 0) * FP + lrow] = q4.x;
        Qt[(dh0 + 1) * FP + lrow] = q4.y;
        Qt[(dh0 + 2) * FP + lrow] = q4.z;
        Qt[(dh0 + 3) * FP + lrow] = q4.w;
    }

    float m_i[4], l_i[4], o_acc[4][4];
#pragma unroll
    for (int i = 0; i < 4; i++) {
        m_i[i] = -1e30f; l_i[i] = 0.f;
#pragma unroll
        for (int j = 0; j < 4; j++) o_acc[i][j] = 0.f;
    }

    for (int kb = 0; kb < S_ / 64; kb++) {
        __syncthreads();
#pragma unroll
        for (int i = 0; i < 4; i++) {
            const int dh0 = 4 * (lq + 4 * i);
            float4 k4 = *(const float4*)(Kg + (size_t)(kb * 64 + lrow) * DH_ + dh0);
            KtPs[(dh0 + 0) * FP + lrow] = k4.x;
            KtPs[(dh0 + 1) * FP + lrow] = k4.y;
            KtPs[(dh0 + 2) * FP + lrow] = k4.z;
            KtPs[(dh0 + 3) * FP + lrow] = k4.w;
            float4 v4 = *(const float4*)(Vg + (size_t)(kb * 64 + lrow) * DH_ + dh0);
            *(float4*)&Vs[lrow * FP + dh0] = v4;
        }
        if (t < 64) msk[t] = mask[b * S_ + kb * 64 + t];
        __syncthreads();

        float s[4][4];
#pragma unroll
        for (int i = 0; i < 4; i++)
#pragma unroll
            for (int j = 0; j < 4; j++) s[i][j] = 0.f;
#pragma unroll 8
        for (int kk = 0; kk < 64; kk++) {
            float4 qv = *(const float4*)&Qt[kk * FP + (ty << 2)];
            float4 kv = *(const float4*)&KtPs[kk * FP + (tx << 2)];
            s[0][0] += qv.x * kv.x; s[0][1] += qv.x * kv.y;
            s[0][2] += qv.x * kv.z; s[0][3] += qv.x * kv.w;
            s[1][0] += qv.y * kv.x; s[1][1] += qv.y * kv.y;
            s[1][2] += qv.y * kv.z; s[1][3] += qv.y * kv.w;
            s[2][0] += qv.z * kv.x; s[2][1] += qv.z * kv.y;
            s[2][2] += qv.z * kv.z; s[2][3] += qv.z * kv.w;
            s[3][0] += qv.w * kv.x; s[3][1] += qv.w * kv.y;
            s[3][2] += qv.w * kv.z; s[3][3] += qv.w * kv.w;
        }

#pragma unroll
        for (int j = 0; j < 4; j++) {
            const bool ok = msk[(tx << 2) + j] != 0;
#pragma unroll
            for (int i = 0; i < 4; i++)
                s[i][j] = ok ? s[i][j] * 0.125f : -1e9f;
        }

        float pv[4][4];
#pragma unroll
        for (int i = 0; i < 4; i++) {
            float rmax = fmaxf(fmaxf(s[i][0], s[i][1]), fmaxf(s[i][2], s[i][3]));
#pragma unroll
            for (int d = 1; d <= 8; d <<= 1)
                rmax = fmaxf(rmax, __shfl_xor_sync(0xffffffffu, rmax, d));
            const float mnew  = fmaxf(m_i[i], rmax);
            const float alpha = __expf(m_i[i] - mnew);
            float rsum = 0.f;
#pragma unroll
            for (int j = 0; j < 4; j++) {
                pv[i][j] = __expf(s[i][j] - mnew);
                rsum += pv[i][j];
            }
#pragma unroll
            for (int d = 1; d <= 8; d <<= 1)
                rsum += __shfl_xor_sync(0xffffffffu, rsum, d);
            l_i[i] = l_i[i] * alpha + rsum;
            m_i[i] = mnew;
#pragma unroll
            for (int j = 0; j < 4; j++) o_acc[i][j] *= alpha;
        }

        __syncthreads();
#pragma unroll
        for (int i = 0; i < 4; i++)
            *(float4*)&KtPs[((ty << 2) + i) * FP + (tx << 2)] =
                make_float4(pv[i][0], pv[i][1], pv[i][2], pv[i][3]);
        __syncthreads();

#pragma unroll 8
        for (int jj = 0; jj < 64; jj++) {
            const float4 vv = *(const float4*)&Vs[jj * FP + (tx << 2)];
            const float p0 = KtPs[((ty << 2) + 0) * FP + jj];
            const float p1 = KtPs[((ty << 2) + 1) * FP + jj];
            const float p2 = KtPs[((ty << 2) + 2) * FP + jj];
            const float p3 = KtPs[((ty << 2) + 3) * FP + jj];
            o_acc[0][0] += p0 * vv.x; o_acc[0][1] += p0 * vv.y;
            o_acc[0][2] += p0 * vv.z; o_acc[0][3] += p0 * vv.w;
            o_acc[1][0] += p1 * vv.x; o_acc[1][1] += p1 * vv.y;
            o_acc[1][2] += p1 * vv.z; o_acc[1][3] += p1 * vv.w;
            o_acc[2][0] += p2 * vv.x; o_acc[2][1] += p2 * vv.y;
            o_acc[2][2] += p2 * vv.z; o_acc[2][3] += p2 * vv.w;
            o_acc[3][0] += p3 * vv.x; o_acc[3][1] += p3 * vv.y;
            o_acc[3][2] += p3 * vv.z; o_acc[3][3] += p3 * vv.w;
        }
    }

#pragma unroll
    for (int i = 0; i < 4; i++) {
        const float inv = 1.f / l_i[i];
        const int sg = qb * 64 + (ty << 2) + i;
#pragma unroll
        for (int j = 0; j < 4; j++) {
            out[((size_t)(b * S_ + sg)) * D_ + h * DH_ + (tx << 2) + j] =
                o_acc[i][j] * inv;
        }
    }
}

// ---------------------------------------------------------------------------
// Launch
// ---------------------------------------------------------------------------
extern "C" void kernel_launch(void* const* d_in, const int* in_sizes, int n_in,
                              void* d_out, int out_size)
{
    (void)in_sizes; (void)n_in; (void)out_size;
    const float* x    = (const float*)d_in[0];
    const int*   mask = (const int*)  d_in[1];
    const float* Wq   = (const float*)d_in[2];
    const float* bq   = (const float*)d_in[3];
    const float* Wk   = (const float*)d_in[4];
    const float* bk   = (const float*)d_in[5];
    const float* Wv   = (const float*)d_in[6];
    const float* bv   = (const float*)d_in[7];
    const float* Wo   = (const float*)d_in[8];
    const float* bo   = (const float*)d_in[9];
    float* out = (float*)d_out;

    float *qp, *kp, *vp, *ap;
    cudaGetSymbolAddress((void**)&qp, g_q);
    cudaGetSymbolAddress((void**)&kp, g_k);
    cudaGetSymbolAddress((void**)&vp, g_v);
    cudaGetSymbolAddress((void**)&ap, g_att);

    static int attr_done = 0;
    if (!attr_done) {
        cudaFuncSetAttribute(flash_kernel,
                             cudaFuncAttributeMaxDynamicSharedMemorySize, FLASH_SMEM);
        attr_done = 1;
    }

    // Fused Q/K/V projections (fp16 HMMA probe)
    gemmh<<<dim3(D_ / 128, N_ / 128, 3), 256>>>(
        x, Wq, Wk, Wv, bq, bk, bv, qp, kp, vp, 1);

    flash_kernel<<<dim3(S_ / 64, H_, B_), 256, FLASH_SMEM>>>(mask, ap);

    // Output projection
    gemmh<<<dim3(D_ / 128, N_ / 128, 1), 256>>>(
        ap, Wo, Wo, Wo, bo, bo, bo, out, out, out, 0);
}

// round 15
// speedup vs baseline: 3.8394x; 1.8723x over previous
#include <cuda_runtime.h>
#include <cuda_fp16.h>
#include <cstdint>

// Problem constants
#define B_   2
#define S_   2048
#define D_   1024
#define H_   16
#define DH_  64
#define N_   (B_ * S_)   // 4096 tokens
#define K_   1024

// ---------------------------------------------------------------------------
// Scratch (device globals — no allocation allowed)
// ---------------------------------------------------------------------------
__device__ float g_q[B_ * H_ * S_ * DH_];   // [b][h][s][dh]
__device__ float g_k[B_ * H_ * S_ * DH_];
__device__ float g_v[B_ * H_ * S_ * DH_];
__device__ float g_att[N_ * D_];            // [n][h*64+dh]

// ---------------------------------------------------------------------------
// fp16 HMMA helpers (layout verified by R13's passing gemmh)
// ---------------------------------------------------------------------------
__device__ __forceinline__ uint32_t f2h2(float x, float y) {
    __half2 h = __floats2half2_rn(x, y);
    return *(uint32_t*)&h;
}
__device__ __forceinline__ void mma_f16(float* c, const uint32_t* a, const uint32_t* b) {
    asm volatile(
        "mma.sync.aligned.m16n8k16.row.col.f32.f16.f16.f32 "
        "{%0,%1,%2,%3}, {%4,%5,%6,%7}, {%8,%9}, {%0,%1,%2,%3};"
        : "+f"(c[0]), "+f"(c[1]), "+f"(c[2]), "+f"(c[3])
        : "r"(a[0]), "r"(a[1]), "r"(a[2]), "r"(a[3]), "r"(b[0]), "r"(b[1]));
}

// ---------------------------------------------------------------------------
// fp16 mma.sync TN GEMM (R13-proven): C[n,o] = sum_k A[n,k]*W[o,k] + bias[o]
// ---------------------------------------------------------------------------
#define KPH 40

__global__ void __launch_bounds__(256)
gemmh(const float* __restrict__ A,
      const float* __restrict__ W0, const float* __restrict__ W1,
      const float* __restrict__ W2,
      const float* __restrict__ b0, const float* __restrict__ b1,
      const float* __restrict__ b2,
      float* __restrict__ C0, float* __restrict__ C1, float* __restrict__ C2,
      int scatter)
{
    __shared__ uint16_t Ah[128 * KPH];
    __shared__ uint16_t Bh[128 * KPH];

    const int z = blockIdx.z;
    const float* W    = (z == 0) ? W0 : (z == 1) ? W1 : W2;
    const float* bias = (z == 0) ? b0 : (z == 1) ? b1 : b2;
    float*       C    = (z == 0) ? C0 : (z == 1) ? C1 : C2;

    const int t    = threadIdx.x;
    const int wid  = t >> 5;
    const int lane = t & 31;
    const int bn = blockIdx.x;
    const int bm = blockIdx.y;

    const int wr = (wid & 1) << 6;
    const int wc = (wid >> 1) << 5;
    const int g   = lane >> 2;
    const int tig = lane & 3;

    const int lrow = t >> 1;
    const int lkc  = (t & 1) * 16;

    const float* Ag = A + (size_t)(bm * 128 + lrow) * K_ + lkc;
    const float* Wg = W + (size_t)(bn * 128 + lrow) * K_ + lkc;

    float acc[4][4][4];
#pragma unroll
    for (int mt = 0; mt < 4; mt++)
#pragma unroll
        for (int nt = 0; nt < 4; nt++)
#pragma unroll
            for (int r = 0; r < 4; r++) acc[mt][nt][r] = 0.f;

    float4 pa[4], pb[4];
#pragma unroll
    for (int i = 0; i < 4; i++) {
        pa[i] = *(const float4*)(Ag + 4 * i);
        pb[i] = *(const float4*)(Wg + 4 * i);
    }

    for (int c = 0; c < 32; c++) {
        __syncthreads();
#pragma unroll
        for (int i = 0; i < 4; i++) {
            *(uint2*)&Ah[lrow * KPH + lkc + 4 * i] =
                make_uint2(f2h2(pa[i].x, pa[i].y), f2h2(pa[i].z, pa[i].w));
            *(uint2*)&Bh[lrow * KPH + lkc + 4 * i] =
                make_uint2(f2h2(pb[i].x, pb[i].y), f2h2(pb[i].z, pb[i].w));
        }
        __syncthreads();
        if (c < 31) {
            const float* An = Ag + (size_t)(c + 1) * 32;
            const float* Wn = Wg + (size_t)(c + 1) * 32;
#pragma unroll
            for (int i = 0; i < 4; i++) {
                pa[i] = *(const float4*)(An + 4 * i);
                pb[i] = *(const float4*)(Wn + 4 * i);
            }
        }
#pragma unroll
        for (int ks = 0; ks < 2; ks++) {
            const int k0 = 16 * ks + 2 * tig;
            uint32_t af[4][4], bf[4][2];
#pragma unroll
            for (int mt = 0; mt < 4; mt++) {
                const int r = wr + 16 * mt + g;
                af[mt][0] = *(const uint32_t*)&Ah[r * KPH + k0];
                af[mt][1] = *(const uint32_t*)&Ah[(r + 8) * KPH + k0];
                af[mt][2] = *(const uint32_t*)&Ah[r * KPH + k0 + 8];
                af[mt][3] = *(const uint32_t*)&Ah[(r + 8) * KPH + k0 + 8];
            }
#pragma unroll
            for (int nt = 0; nt < 4; nt++) {
                const int o = wc + 8 * nt + g;
                bf[nt][0] = *(const uint32_t*)&Bh[o * KPH + k0];
                bf[nt][1] = *(const uint32_t*)&Bh[o * KPH + k0 + 8];
            }
#pragma unroll
            for (int mt = 0; mt < 4; mt++)
#pragma unroll
                for (int nt = 0; nt < 4; nt++)
                    mma_f16(acc[mt][nt], af[mt], bf[nt]);
        }
    }

    const int rbase = bm * 128 + wr + g;
    const int cbase = bn * 128 + wc + 2 * tig;
#pragma unroll
    for (int mt = 0; mt < 4; mt++) {
#pragma unroll
        for (int nt = 0; nt < 4; nt++) {
            const int col = cbase + nt * 8;
            const float bx = bias[col], by = bias[col + 1];
#pragma unroll
            for (int h2 = 0; h2 < 2; h2++) {
                const int n = rbase + mt * 16 + 8 * h2;
                float2 v;
                v.x = acc[mt][nt][2 * h2 + 0] + bx;
                v.y = acc[mt][nt][2 * h2 + 1] + by;
                if (scatter) {
                    const int b  = n >> 11;
                    const int s  = n & (S_ - 1);
                    const int hh = col >> 6;
                    const int dh = col & 63;
                    *(float2*)(C + (((size_t)(b * H_ + hh)) * S_ + s) * DH_ + dh) = v;
                } else {
                    *(float2*)(C + (size_t)n * D_ + col) = v;
                }
            }
        }
    }
}

// ---------------------------------------------------------------------------
// HMMA flash attention: 64 q-rows/CTA, 4 warps (16 rows each), 64-key blocks.
// QK^T and P@V on m16n8k16; softmax in fp32 on register fragments; P stays
// in registers (QK accumulator layout == PV A-fragment layout).
// smem strides of 72 halves -> conflict-free fragment loads.
// ---------------------------------------------------------------------------
#define FSTR 72

__global__ void __launch_bounds__(128)
flash_h(const int* __restrict__ mask, float* __restrict__ out)
{
    __shared__ uint16_t Qh[64 * FSTR];
    __shared__ uint16_t Kh[64 * FSTR];
    __shared__ uint16_t Vt[64 * FSTR];   // transposed: [dh][key]
    __shared__ int      msk[64];

    const int qb = blockIdx.x;
    const int h  = blockIdx.y;
    const int b  = blockIdx.z;

    const float* Qg = g_q + ((size_t)(b * H_ + h)) * S_ * DH_;
    const float* Kg = g_k + ((size_t)(b * H_ + h)) * S_ * DH_;
    const float* Vg = g_v + ((size_t)(b * H_ + h)) * S_ * DH_;

    const int t    = threadIdx.x;
    const int wid  = t >> 5;
    const int lane = t & 31;
    const int g    = lane >> 2;
    const int tig  = lane & 3;

    // Loader mapping: row = t>>1 (0..63), dh half = (t&1)*32
    const int lr = t >> 1;
    const int dc = (t & 1) * 32;

    // Load Q tile -> fp16 smem
    {
        const float* Qp = Qg + (size_t)(qb * 64 + lr) * DH_ + dc;
#pragma unroll
        for (int i = 0; i < 8; i++) {
            float4 q4 = *(const float4*)(Qp + 4 * i);
            *(uint2*)&Qh[lr * FSTR + dc + 4 * i] =
                make_uint2(f2h2(q4.x, q4.y), f2h2(q4.z, q4.w));
        }
    }
    __syncthreads();

    // Q fragments: rows 16*wid+g / +8, dh 16kt..+15
    uint32_t qf[4][4];
#pragma unroll
    for (int kt = 0; kt < 4; kt++) {
        const int base = (16 * wid + g) * FSTR + 16 * kt + 2 * tig;
        qf[kt][0] = *(const uint32_t*)&Qh[base];
        qf[kt][1] = *(const uint32_t*)&Qh[base + 8 * FSTR];
        qf[kt][2] = *(const uint32_t*)&Qh[base + 8];
        qf[kt][3] = *(const uint32_t*)&Qh[base + 8 * FSTR + 8];
    }

    float o[8][4];
#pragma unroll
    for (int nt = 0; nt < 8; nt++)
#pragma unroll
        for (int r = 0; r < 4; r++) o[nt][r] = 0.f;
    float mA = -1e30f, mB = -1e30f, lA = 0.f, lB = 0.f;

    for (int kb = 0; kb < S_ / 64; kb++) {
        __syncthreads();
        // Load K (row-major fp16) and V (transposed fp16)
        {
            const float* Kp = Kg + (size_t)(kb * 64 + lr) * DH_ + dc;
            const float* Vp = Vg + (size_t)(kb * 64 + lr) * DH_ + dc;
#pragma unroll
            for (int i = 0; i < 8; i++) {
                float4 k4 = *(const float4*)(Kp + 4 * i);
                *(uint2*)&Kh[lr * FSTR + dc + 4 * i] =
                    make_uint2(f2h2(k4.x, k4.y), f2h2(k4.z, k4.w));
                float4 v4 = *(const float4*)(Vp + 4 * i);
                const int d0 = dc + 4 * i;
                *(__half*)&Vt[(d0 + 0) * FSTR + lr] = __float2half(v4.x);
                *(__half*)&Vt[(d0 + 1) * FSTR + lr] = __float2half(v4.y);
                *(__half*)&Vt[(d0 + 2) * FSTR + lr] = __float2half(v4.z);
                *(__half*)&Vt[(d0 + 3) * FSTR + lr] = __float2half(v4.w);
            }
        }
        if (t < 64) msk[t] = mask[b * S_ + kb * 64 + t];
        __syncthreads();

        // ---- QK^T: sc[nt] covers keys 8nt..8nt+7 ----
        float sc[8][4];
#pragma unroll
        for (int nt = 0; nt < 8; nt++)
#pragma unroll
            for (int r = 0; r < 4; r++) sc[nt][r] = 0.f;
#pragma unroll
        for (int kt = 0; kt < 4; kt++) {
#pragma unroll
            for (int nt = 0; nt < 8; nt++) {
                uint32_t bf[2];
                const int base = (8 * nt + g) * FSTR + 16 * kt + 2 * tig;
                bf[0] = *(const uint32_t*)&Kh[base];
                bf[1] = *(const uint32_t*)&Kh[base + 8];
                mma_f16(sc[nt], qf[kt], bf);
            }
        }

        // ---- scale + mask + online softmax (rows g and g+8) ----
        float mxA = -1e30f, mxB = -1e30f;
#pragma unroll
        for (int nt = 0; nt < 8; nt++) {
            const bool ok0 = msk[8 * nt + 2 * tig] != 0;
            const bool ok1 = msk[8 * nt + 2 * tig + 1] != 0;
            sc[nt][0] = ok0 ? sc[nt][0] * 0.125f : -1e9f;
            sc[nt][1] = ok1 ? sc[nt][1] * 0.125f : -1e9f;
            sc[nt][2] = ok0 ? sc[nt][2] * 0.125f : -1e9f;
            sc[nt][3] = ok1 ? sc[nt][3] * 0.125f : -1e9f;
            mxA = fmaxf(mxA, fmaxf(sc[nt][0], sc[nt][1]));
            mxB = fmaxf(mxB, fmaxf(sc[nt][2], sc[nt][3]));
        }
        mxA = fmaxf(mxA, __shfl_xor_sync(0xffffffffu, mxA, 1));
        mxA = fmaxf(mxA, __shfl_xor_sync(0xffffffffu, mxA, 2));
        mxB = fmaxf(mxB, __shfl_xor_sync(0xffffffffu, mxB, 1));
        mxB = fmaxf(mxB, __shfl_xor_sync(0xffffffffu, mxB, 2));

        const float mnA = fmaxf(mA, mxA);
        const float mnB = fmaxf(mB, mxB);
        const float aA = __expf(mA - mnA);
        const float aB = __expf(mB - mnB);
        float sumA = 0.f, sumB = 0.f;
#pragma unroll
        for (int nt = 0; nt < 8; nt++) {
            sc[nt][0] = __expf(sc[nt][0] - mnA);
            sc[nt][1] = __expf(sc[nt][1] - mnA);
            sc[nt][2] = __expf(sc[nt][2] - mnB);
            sc[nt][3] = __expf(sc[nt][3] - mnB);
            sumA += sc[nt][0] + sc[nt][1];
            sumB += sc[nt][2] + sc[nt][3];
        }
        sumA += __shfl_xor_sync(0xffffffffu, sumA, 1);
        sumA += __shfl_xor_sync(0xffffffffu, sumA, 2);
        sumB += __shfl_xor_sync(0xffffffffu, sumB, 1);
        sumB += __shfl_xor_sync(0xffffffffu, sumB, 2);
        lA = lA * aA + sumA; mA = mnA;
        lB = lB * aB + sumB; mB = mnB;
#pragma unroll
        for (int nt = 0; nt < 8; nt++) {
            o[nt][0] *= aA; o[nt][1] *= aA;
            o[nt][2] *= aB; o[nt][3] *= aB;
        }

        // ---- pack P fragments (register-only) ----
        uint32_t pa[4][4];
#pragma unroll
        for (int kt = 0; kt < 4; kt++) {
            pa[kt][0] = f2h2(sc[2 * kt][0],     sc[2 * kt][1]);
            pa[kt][1] = f2h2(sc[2 * kt][2],     sc[2 * kt][3]);
            pa[kt][2] = f2h2(sc[2 * kt + 1][0], sc[2 * kt + 1][1]);
            pa[kt][3] = f2h2(sc[2 * kt + 1][2], sc[2 * kt + 1][3]);
        }

        // ---- O += P @ V : o[nt] covers dh 8nt..8nt+7 ----
#pragma unroll
        for (int kt = 0; kt < 4; kt++) {
#pragma unroll
            for (int nt = 0; nt < 8; nt++) {
                uint32_t bf[2];
                const int base = (8 * nt + g) * FSTR + 16 * kt + 2 * tig;
                bf[0] = *(const uint32_t*)&Vt[base];
                bf[1] = *(const uint32_t*)&Vt[base + 8];
                mma_f16(o[nt], pa[kt], bf);
            }
        }
    }

    // Epilogue: normalize, write [n][h*64+dh]
    const float invA = 1.f / lA;
    const float invB = 1.f / lB;
    const int rowA = qb * 64 + 16 * wid + g;
    const int rowB = rowA + 8;
#pragma unroll
    for (int nt = 0; nt < 8; nt++) {
        const int col = 8 * nt + 2 * tig;
        float2 va = make_float2(o[nt][0] * invA, o[nt][1] * invA);
        float2 vb = make_float2(o[nt][2] * invB, o[nt][3] * invB);
        *(float2*)(out + ((size_t)(b * S_ + rowA)) * D_ + h * DH_ + col) = va;
        *(float2*)(out + ((size_t)(b * S_ + rowB)) * D_ + h * DH_ + col) = vb;
    }
}

// ---------------------------------------------------------------------------
// Launch
// ---------------------------------------------------------------------------
extern "C" void kernel_launch(void* const* d_in, const int* in_sizes, int n_in,
                              void* d_out, int out_size)
{
    (void)in_sizes; (void)n_in; (void)out_size;
    const float* x    = (const float*)d_in[0];
    const int*   mask = (const int*)  d_in[1];
    const float* Wq   = (const float*)d_in[2];
    const float* bq   = (const float*)d_in[3];
    const float* Wk   = (const float*)d_in[4];
    const float* bk   = (const float*)d_in[5];
    const float* Wv   = (const float*)d_in[6];
    const float* bv   = (const float*)d_in[7];
    const float* Wo   = (const float*)d_in[8];
    const float* bo   = (const float*)d_in[9];
    float* out = (float*)d_out;

    float *qp, *kp, *vp, *ap;
    cudaGetSymbolAddress((void**)&qp, g_q);
    cudaGetSymbolAddress((void**)&kp, g_k);
    cudaGetSymbolAddress((void**)&vp, g_v);
    cudaGetSymbolAddress((void**)&ap, g_att);

    // Fused Q/K/V projections (fp16 HMMA)
    gemmh<<<dim3(D_ / 128, N_ / 128, 3), 256>>>(
        x, Wq, Wk, Wv, bq, bk, bv, qp, kp, vp, 1);

    // HMMA flash attention
    flash_h<<<dim3(S_ / 64, H_, B_), 128>>>(mask, ap);

    // Output projection
    gemmh<<<dim3(D_ / 128, N_ / 128, 1), 256>>>(
        ap, Wo, Wo, Wo, bo, bo, bo, out, out, out, 0);
}